// round 4
// baseline (speedup 1.0000x reference)
#include <cuda_runtime.h>
#include <cuda_bf16.h>

// B=16, N_VEC=2048, N_DIM=32, N_W=4, N_HID=128, VOCAB=32000, N_CLASS=10

typedef unsigned long long u64;

__device__ __forceinline__ u64 fma2(u64 a, u64 b, u64 c) {
    u64 d;
    asm("fma.rn.f32x2 %0, %1, %2, %3;" : "=l"(d) : "l"(a), "l"(b), "l"(c));
    return d;
}
__device__ __forceinline__ u64 pack2(float lo, float hi) {
    u64 r;
    asm("mov.b64 %0, {%1, %2};" : "=l"(r) : "f"(lo), "f"(hi));
    return r;
}
__device__ __forceinline__ float2 unpack2(u64 v) {
    float2 f;
    asm("mov.b64 {%0, %1}, %2;" : "=f"(f.x), "=f"(f.y) : "l"(v));
    return f;
}

// ---------- scratch (device globals; allocation is forbidden) ----------
__device__ float g_X [16 * 2048 * 32];
__device__ float g_VA[16 * 2048 * 32];
__device__ float g_VB[16 * 2048 * 32];
__device__ float g_Upart[16 * 16 * 129 * 32];   // [b][chunk][129][32] (row 128 = bias c)
__device__ float g_U[16 * 129 * 32];            // [b][129][32]
__device__ float g_partF[16 * 32 * 10];
__device__ unsigned g_tick;

// ---------- X = emb[data], with per-block int64/int32 detection ----------
__global__ __launch_bounds__(256) void k_gather(const int* __restrict__ d32,
                                                const float* __restrict__ emb) {
    __shared__ int s_is64;
    int tid = threadIdx.x;
    if (tid == 0) s_is64 = 1;
    __syncthreads();
    if (tid < 32) { if (d32[2 * tid + 1] != 0) s_is64 = 0; }
    __syncthreads();
    int t = blockIdx.x * 256 + tid;              // over 16*2048*8 float4s
    int row = t >> 3, q = t & 7;
    int idx = s_is64 ? d32[row * 2] : d32[row];
    float4 v = *reinterpret_cast<const float4*>(emb + (size_t)idx * 32 + q * 4);
    *reinterpret_cast<float4*>(g_X + (size_t)row * 32 + q * 4) = v;
}

// ---------- U partials: U[b] = fw2[layer] @ V[b], c[b] = fb2[layer] . V[b] ----------
__global__ __launch_bounds__(256) void k_upart(const float* __restrict__ fw2,
                                               const float* __restrict__ fb2,
                                               int vin_sel, int layer) {
    __shared__ __align__(16) float VsT[32 * 130];   // [d][m], pad 130
    int b = blockIdx.y, ch = blockIdx.x, tid = threadIdx.x;
    int m0 = ch * 128;
    const float* Vin = (vin_sel == 0) ? g_X : (vin_sel == 1 ? g_VA : g_VB);
    const float* vg = Vin + ((size_t)(b * 2048 + m0)) * 32;
#pragma unroll
    for (int it = 0; it < 16; ++it) {
        int t = tid + it * 256;                  // t = m*32 + d
        VsT[(t & 31) * 130 + (t >> 5)] = vg[t];
    }
    __syncthreads();

    int d0 = (tid & 7) * 4, h0 = (tid >> 3) * 4;
    const float* w0 = fw2 + ((size_t)(layer * 128 + h0)) * 2048 + m0;

    u64 acc[4][4];
#pragma unroll
    for (int a = 0; a < 4; ++a)
#pragma unroll
        for (int c = 0; c < 4; ++c) acc[a][c] = 0ull;

#pragma unroll 8
    for (int m = 0; m < 64; ++m) {               // 2 K-elems per iter
        u64 va[4];
#pragma unroll
        for (int kd = 0; kd < 4; ++kd)
            va[kd] = *reinterpret_cast<const u64*>(VsT + (d0 + kd) * 130 + 2 * m);
#pragma unroll
        for (int kh = 0; kh < 4; ++kh) {
            u64 w = *reinterpret_cast<const u64*>(w0 + (size_t)kh * 2048 + 2 * m);
#pragma unroll
            for (int kd = 0; kd < 4; ++kd) acc[kh][kd] = fma2(w, va[kd], acc[kh][kd]);
        }
    }

    float* up = g_Upart + (((size_t)(b * 16 + ch)) * 129 + h0) * 32 + d0;
#pragma unroll
    for (int kh = 0; kh < 4; ++kh) {
        float2 s0 = unpack2(acc[kh][0]), s1 = unpack2(acc[kh][1]);
        float2 s2 = unpack2(acc[kh][2]), s3 = unpack2(acc[kh][3]);
        *reinterpret_cast<float4*>(up + (size_t)kh * 32) =
            make_float4(s0.x + s0.y, s1.x + s1.y, s2.x + s2.y, s3.x + s3.y);
    }

    if (tid < 8) {                               // bias row c (h == 128)
        int db = tid * 4;
        const float* wb = fb2 + (size_t)layer * 2048 + m0;
        u64 a[4] = {0ull, 0ull, 0ull, 0ull};
        for (int m = 0; m < 64; ++m) {
            u64 w2 = *reinterpret_cast<const u64*>(wb + 2 * m);
#pragma unroll
            for (int k = 0; k < 4; ++k)
                a[k] = fma2(w2, *reinterpret_cast<const u64*>(VsT + (db + k) * 130 + 2 * m), a[k]);
        }
        float2 s0 = unpack2(a[0]), s1 = unpack2(a[1]), s2 = unpack2(a[2]), s3 = unpack2(a[3]);
        *reinterpret_cast<float4*>(g_Upart + (((size_t)(b * 16 + ch)) * 129 + 128) * 32 + db) =
            make_float4(s0.x + s0.y, s1.x + s1.y, s2.x + s2.y, s3.x + s3.y);
    }
}

// ---------- reduce split-K partials (vectorized, MLP=16) ----------
__global__ __launch_bounds__(256) void k_ured() {
    int idx = blockIdx.x * 256 + threadIdx.x;    // over 16*1032 float4s
    if (idx >= 16 * 1032) return;
    int b = idx / 1032, r4 = idx - b * 1032;
    const float4* base = reinterpret_cast<const float4*>(g_Upart) + (size_t)b * 16 * 1032 + r4;
    float4 s = make_float4(0.f, 0.f, 0.f, 0.f);
#pragma unroll
    for (int c = 0; c < 16; ++c) {
        float4 v = base[(size_t)c * 1032];
        s.x += v.x; s.y += v.y; s.z += v.z; s.w += v.w;
    }
    reinterpret_cast<float4*>(g_U)[(size_t)b * 1032 + r4] = s;
}

// ---------- fused: H = gelu(X @ fw1 + fb1); V' = H @ U + c ----------
// 64 rows/block, 128 threads, grid (32,16). H stored pre-splatted (u64) in smem.
// dyn smem: Xs [64*32] f32 (8KB) | Us [129*32] f32 (16.5KB) | Hs [128][66] u64 (67.6KB)
__global__ __launch_bounds__(128) void k_vupd(const float* __restrict__ fw1,
                                              const float* __restrict__ fb1,
                                              int vout_sel, int layer) {
    extern __shared__ __align__(16) char smraw[];
    float* Xs = reinterpret_cast<float*>(smraw);            // [64][32]
    float* Us = Xs + 64 * 32;                               // [129][32]
    u64*   Hs = reinterpret_cast<u64*>(smraw + 24704);      // [128][66] splatted
    int b = blockIdx.y, n0 = blockIdx.x * 64, tid = threadIdx.x;

    const float4* xg = reinterpret_cast<const float4*>(g_X + ((size_t)(b * 2048 + n0)) * 32);
#pragma unroll
    for (int it = 0; it < 4; ++it)
        reinterpret_cast<float4*>(Xs)[tid + it * 128] = xg[tid + it * 128];
    const float4* Ug = reinterpret_cast<const float4*>(g_U + (size_t)b * 4128);
#pragma unroll
    for (int it = 0; it < 8; ++it)
        reinterpret_cast<float4*>(Us)[tid + it * 128] = Ug[tid + it * 128];
    if (tid < 8) reinterpret_cast<float4*>(Us)[1024 + tid] = Ug[1024 + tid];
    __syncthreads();

    // phase 1: thread = 2 adjacent cols (jA,jB) x 32 rows; f32x2 along d; LDS.128 X reads.
    {
        int jA = (tid & 63) * 2, jB = jA + 1;
        int rbase = (tid >> 6) * 32;
        const float* wbase = fw1 + (size_t)layer * 4096;
        u64 wcA[16], wcB[16];
#pragma unroll
        for (int k = 0; k < 16; ++k) {
            float2 r0 = *reinterpret_cast<const float2*>(wbase + (2 * k) * 128 + jA);
            float2 r1 = *reinterpret_cast<const float2*>(wbase + (2 * k + 1) * 128 + jA);
            wcA[k] = pack2(r0.x, r1.x);
            wcB[k] = pack2(r0.y, r1.y);
        }
        float bjA = fb1[layer * 128 + jA], bjB = fb1[layer * 128 + jB];
#pragma unroll 4
        for (int rr = 0; rr < 32; ++rr) {
            int r = rbase + rr;
            const ulonglong2* xq = reinterpret_cast<const ulonglong2*>(Xs + r * 32);
            u64 aA = 0ull, aB = 0ull;
#pragma unroll
            for (int k = 0; k < 8; ++k) {
                ulonglong2 x = xq[k];
                aA = fma2(x.x, wcA[2 * k], aA);
                aB = fma2(x.x, wcB[2 * k], aB);
                aA = fma2(x.y, wcA[2 * k + 1], aA);
                aB = fma2(x.y, wcB[2 * k + 1], aB);
            }
            float2 sA = unpack2(aA), sB = unpack2(aB);
            float xA = sA.x + sA.y + bjA;
            float xB = sB.x + sB.y + bjB;
            float hA = 0.5f * xA * (1.0f + erff(xA * 0.70710678118654752f));
            float hB = 0.5f * xB * (1.0f + erff(xB * 0.70710678118654752f));
            Hs[jA * 66 + r] = pack2(hA, hA);
            Hs[jB * 66 + r] = pack2(hB, hB);
        }
    }
    __syncthreads();

    // phase 2: thread tile 4 rows x 4 cols; per j: 3x LDS.128 + 8 FFMA2, no packs.
    {
        int r0 = (tid >> 3) * 4, d0 = (tid & 7) * 4;
        u64 a00 = 0ull, a01 = 0ull, a10 = 0ull, a11 = 0ull;
        u64 a20 = 0ull, a21 = 0ull, a30 = 0ull, a31 = 0ull;
#pragma unroll 4
        for (int j = 0; j < 128; ++j) {
            ulonglong2 h01 = *reinterpret_cast<const ulonglong2*>(Hs + j * 66 + r0);
            ulonglong2 h23 = *reinterpret_cast<const ulonglong2*>(Hs + j * 66 + r0 + 2);
            ulonglong2 u   = *reinterpret_cast<const ulonglong2*>(Us + j * 32 + d0);
            a00 = fma2(h01.x, u.x, a00);  a01 = fma2(h01.x, u.y, a01);
            a10 = fma2(h01.y, u.x, a10);  a11 = fma2(h01.y, u.y, a11);
            a20 = fma2(h23.x, u.x, a20);  a21 = fma2(h23.x, u.y, a21);
            a30 = fma2(h23.y, u.x, a30);  a31 = fma2(h23.y, u.y, a31);
        }
        float* Vout = (vout_sel == 1) ? g_VA : g_VB;
        float4 c4 = *reinterpret_cast<const float4*>(Us + 4096 + d0);
        u64 accs[4][2] = {{a00, a01}, {a10, a11}, {a20, a21}, {a30, a31}};
#pragma unroll
        for (int rr = 0; rr < 4; ++rr) {
            float2 p0 = unpack2(accs[rr][0]), p1 = unpack2(accs[rr][1]);
            *reinterpret_cast<float4*>(Vout + ((size_t)(b * 2048 + n0 + r0 + rr)) * 32 + d0) =
                make_float4(p0.x + c4.x, p0.y + c4.y, p1.x + c4.z, p1.y + c4.w);
        }
    }
}

// ---------- final projection, fused partial + completion (ticket) ----------
__global__ __launch_bounds__(256) void k_fproj(const float* __restrict__ Wf,
                                               const float* __restrict__ bf,
                                               float* __restrict__ out) {
    __shared__ float wsum[8][10];
    __shared__ int s_last;
    int b = blockIdx.y, ch = blockIdx.x, tid = threadIdx.x;
    int lane = tid & 31, w = tid >> 5;
    float acc[10];
#pragma unroll
    for (int c = 0; c < 10; ++c) acc[c] = 0.f;
    const float* Vb = g_VB + (size_t)b * 65536 + ch * 2048;
#pragma unroll
    for (int q = 0; q < 8; ++q) {
        int k = q * 256 + tid;
        float v = Vb[k];
        const float* wr = Wf + (size_t)(ch * 2048 + k) * 10;
#pragma unroll
        for (int c = 0; c < 10; ++c) acc[c] += v * wr[c];
    }
#pragma unroll
    for (int c = 0; c < 10; ++c) {
#pragma unroll
        for (int s = 16; s > 0; s >>= 1) acc[c] += __shfl_down_sync(0xffffffffu, acc[c], s);
        if (lane == 0) wsum[w][c] = acc[c];
    }
    __syncthreads();
    if (tid < 10) {
        float s = 0.f;
#pragma unroll
        for (int ww = 0; ww < 8; ++ww) s += wsum[ww][tid];
        g_partF[((size_t)(b * 32 + ch)) * 10 + tid] = s;
    }
    __threadfence();
    __syncthreads();
    if (tid == 0) {
        unsigned prev = atomicAdd(&g_tick, 1u);
        s_last = (prev == 511u) ? 1 : 0;
    }
    __syncthreads();
    if (s_last) {
        __threadfence();
        if (tid < 160) {
            int bb = tid / 10, c = tid % 10;
            float s = bf[c];
#pragma unroll
            for (int cc = 0; cc < 32; ++cc) s += g_partF[((size_t)(bb * 32 + cc)) * 10 + c];
            out[tid] = s;
        }
        if (tid == 0) g_tick = 0u;   // reset for next graph replay
    }
}

extern "C" void kernel_launch(void* const* d_in, const int* in_sizes, int n_in,
                              void* d_out, int out_size) {
    const int*   data = (const int*)  d_in[0];
    const float* emb  = (const float*)d_in[1];
    const float* fw1  = (const float*)d_in[2];
    const float* fb1  = (const float*)d_in[3];
    const float* fw2  = (const float*)d_in[4];
    const float* fb2  = (const float*)d_in[5];
    const float* Wf   = (const float*)d_in[6];
    const float* bf   = (const float*)d_in[7];
    float* out = (float*)d_out;

    const int VUPD_SMEM = 24704 + 128 * 66 * 8;   // 92288 bytes
    cudaFuncSetAttribute(k_vupd, cudaFuncAttributeMaxDynamicSharedMemorySize, VUPD_SMEM);

    k_gather<<<1024, 256>>>(data, emb);

    // layers i = 3,2,1,0 ; V ping-pong: X -> VA -> VB -> VA -> VB
    int vin = 0;
    for (int it = 0; it < 4; ++it) {
        int layer = 3 - it;
        int vout = (vin == 1) ? 2 : 1;
        k_upart<<<dim3(16, 16), 256>>>(fw2, fb2, vin, layer);
        k_ured<<<65, 256>>>();
        k_vupd<<<dim3(32, 16), 128, VUPD_SMEM>>>(fw1, fb1, vout, layer);
        vin = vout;
    }

    k_fproj<<<dim3(32, 16), 256>>>(Wf, bf, out);
}

// round 5
// speedup vs baseline: 1.0484x; 1.0484x over previous
#include <cuda_runtime.h>
#include <cuda_bf16.h>

// B=16, N_VEC=2048, N_DIM=32, N_W=4, N_HID=128, VOCAB=32000, N_CLASS=10

typedef unsigned long long u64;

__device__ __forceinline__ u64 fma2(u64 a, u64 b, u64 c) {
    u64 d;
    asm("fma.rn.f32x2 %0, %1, %2, %3;" : "=l"(d) : "l"(a), "l"(b), "l"(c));
    return d;
}
__device__ __forceinline__ u64 pack2(float lo, float hi) {
    u64 r;
    asm("mov.b64 %0, {%1, %2};" : "=l"(r) : "f"(lo), "f"(hi));
    return r;
}
__device__ __forceinline__ float2 unpack2(u64 v) {
    float2 f;
    asm("mov.b64 {%0, %1}, %2;" : "=f"(f.x), "=f"(f.y) : "l"(v));
    return f;
}

// ---------- scratch (device globals; allocation is forbidden) ----------
__device__ float g_X [16 * 2048 * 32];
__device__ float g_VA[16 * 2048 * 32];
__device__ float g_VB[16 * 2048 * 32];
__device__ float g_Upart[16 * 16 * 129 * 32];   // [b][chunk][129][32] (row 128 = bias c)
__device__ float g_U[16 * 129 * 32];            // [b][129][32]
__device__ float g_partF[16 * 32 * 10];
__device__ unsigned g_tick;

// ---------- X = emb[data], with per-block int64/int32 detection ----------
__global__ __launch_bounds__(256) void k_gather(const int* __restrict__ d32,
                                                const float* __restrict__ emb) {
    __shared__ int s_is64;
    int tid = threadIdx.x;
    if (tid == 0) s_is64 = 1;
    __syncthreads();
    if (tid < 32) { if (d32[2 * tid + 1] != 0) s_is64 = 0; }
    __syncthreads();
    int t = blockIdx.x * 256 + tid;              // over 16*2048*8 float4s
    int row = t >> 3, q = t & 7;
    int idx = s_is64 ? d32[row * 2] : d32[row];
    float4 v = *reinterpret_cast<const float4*>(emb + (size_t)idx * 32 + q * 4);
    *reinterpret_cast<float4*>(g_X + (size_t)row * 32 + q * 4) = v;
}

// ---------- U partials: U[b] = fw2[layer] @ V[b], c[b] = fb2[layer] . V[b] ----------
__global__ __launch_bounds__(256) void k_upart(const float* __restrict__ fw2,
                                               const float* __restrict__ fb2,
                                               int vin_sel, int layer) {
    __shared__ __align__(16) float VsT[32 * 130];   // [d][m], pad 130
    int b = blockIdx.y, ch = blockIdx.x, tid = threadIdx.x;
    int m0 = ch * 128;
    const float* Vin = (vin_sel == 0) ? g_X : (vin_sel == 1 ? g_VA : g_VB);
    const float* vg = Vin + ((size_t)(b * 2048 + m0)) * 32;
#pragma unroll
    for (int it = 0; it < 16; ++it) {
        int t = tid + it * 256;                  // t = m*32 + d
        VsT[(t & 31) * 130 + (t >> 5)] = vg[t];
    }
    __syncthreads();

    int d0 = (tid & 7) * 4, h0 = (tid >> 3) * 4;
    const float* w0 = fw2 + ((size_t)(layer * 128 + h0)) * 2048 + m0;

    u64 acc[4][4];
#pragma unroll
    for (int a = 0; a < 4; ++a)
#pragma unroll
        for (int c = 0; c < 4; ++c) acc[a][c] = 0ull;

#pragma unroll 8
    for (int m = 0; m < 64; ++m) {               // 2 K-elems per iter
        u64 va[4];
#pragma unroll
        for (int kd = 0; kd < 4; ++kd)
            va[kd] = *reinterpret_cast<const u64*>(VsT + (d0 + kd) * 130 + 2 * m);
#pragma unroll
        for (int kh = 0; kh < 4; ++kh) {
            u64 w = *reinterpret_cast<const u64*>(w0 + (size_t)kh * 2048 + 2 * m);
#pragma unroll
            for (int kd = 0; kd < 4; ++kd) acc[kh][kd] = fma2(w, va[kd], acc[kh][kd]);
        }
    }

    float* up = g_Upart + (((size_t)(b * 16 + ch)) * 129 + h0) * 32 + d0;
#pragma unroll
    for (int kh = 0; kh < 4; ++kh) {
        float2 s0 = unpack2(acc[kh][0]), s1 = unpack2(acc[kh][1]);
        float2 s2 = unpack2(acc[kh][2]), s3 = unpack2(acc[kh][3]);
        *reinterpret_cast<float4*>(up + (size_t)kh * 32) =
            make_float4(s0.x + s0.y, s1.x + s1.y, s2.x + s2.y, s3.x + s3.y);
    }

    if (tid < 8) {                               // bias row c (h == 128)
        int db = tid * 4;
        const float* wb = fb2 + (size_t)layer * 2048 + m0;
        u64 a[4] = {0ull, 0ull, 0ull, 0ull};
        for (int m = 0; m < 64; ++m) {
            u64 w2 = *reinterpret_cast<const u64*>(wb + 2 * m);
#pragma unroll
            for (int k = 0; k < 4; ++k)
                a[k] = fma2(w2, *reinterpret_cast<const u64*>(VsT + (db + k) * 130 + 2 * m), a[k]);
        }
        float2 s0 = unpack2(a[0]), s1 = unpack2(a[1]), s2 = unpack2(a[2]), s3 = unpack2(a[3]);
        *reinterpret_cast<float4*>(g_Upart + (((size_t)(b * 16 + ch)) * 129 + 128) * 32 + db) =
            make_float4(s0.x + s0.y, s1.x + s1.y, s2.x + s2.y, s3.x + s3.y);
    }
}

// ---------- reduce split-K partials (vectorized, MLP=16) ----------
__global__ __launch_bounds__(256) void k_ured() {
    int idx = blockIdx.x * 256 + threadIdx.x;    // over 16*1032 float4s
    if (idx >= 16 * 1032) return;
    int b = idx / 1032, r4 = idx - b * 1032;
    const float4* base = reinterpret_cast<const float4*>(g_Upart) + (size_t)b * 16 * 1032 + r4;
    float4 s = make_float4(0.f, 0.f, 0.f, 0.f);
#pragma unroll
    for (int c = 0; c < 16; ++c) {
        float4 v = base[(size_t)c * 1032];
        s.x += v.x; s.y += v.y; s.z += v.z; s.w += v.w;
    }
    reinterpret_cast<float4*>(g_U)[(size_t)b * 1032 + r4] = s;
}

// ---------- fused: H = gelu(X @ fw1 + fb1); V' = H @ U + c ----------
// 32 rows/block, 128 threads, grid (64,16). H stored pre-splatted (u64) in smem.
// dyn smem: Xs [32*32] f32 (4KB) | Us [129*32] f32 (16.5KB) | Hs [128][34] u64 (34.8KB)
// total 55424 B -> 4 blocks/SM.
__global__ __launch_bounds__(128) void k_vupd(const float* __restrict__ fw1,
                                              const float* __restrict__ fb1,
                                              int vout_sel, int layer) {
    extern __shared__ __align__(16) char smraw[];
    float* Xs = reinterpret_cast<float*>(smraw);            // [32][32]
    float* Us = Xs + 32 * 32;                               // [129][32]
    u64*   Hs = reinterpret_cast<u64*>(smraw + 20608);      // [128][34] splatted
    int b = blockIdx.y, n0 = blockIdx.x * 32, tid = threadIdx.x;

    const float4* xg = reinterpret_cast<const float4*>(g_X + ((size_t)(b * 2048 + n0)) * 32);
#pragma unroll
    for (int it = 0; it < 2; ++it)
        reinterpret_cast<float4*>(Xs)[tid + it * 128] = xg[tid + it * 128];
    const float4* Ug = reinterpret_cast<const float4*>(g_U + (size_t)b * 4128);
#pragma unroll
    for (int it = 0; it < 8; ++it)
        reinterpret_cast<float4*>(Us)[tid + it * 128] = Ug[tid + it * 128];
    if (tid < 8) reinterpret_cast<float4*>(Us)[1024 + tid] = Ug[1024 + tid];
    __syncthreads();

    // phase 1: thread = 2 adjacent cols (jA,jB) x 16 rows; f32x2 along d; LDS.128 X reads.
    {
        int jA = (tid & 63) * 2, jB = jA + 1;
        int rbase = (tid >> 6) * 16;
        const float* wbase = fw1 + (size_t)layer * 4096;
        u64 wcA[16], wcB[16];
#pragma unroll
        for (int k = 0; k < 16; ++k) {
            float2 r0 = *reinterpret_cast<const float2*>(wbase + (2 * k) * 128 + jA);
            float2 r1 = *reinterpret_cast<const float2*>(wbase + (2 * k + 1) * 128 + jA);
            wcA[k] = pack2(r0.x, r1.x);
            wcB[k] = pack2(r0.y, r1.y);
        }
        float bjA = fb1[layer * 128 + jA], bjB = fb1[layer * 128 + jB];
#pragma unroll 2
        for (int rr = 0; rr < 16; ++rr) {
            int r = rbase + rr;
            const ulonglong2* xq = reinterpret_cast<const ulonglong2*>(Xs + r * 32);
            u64 aA = 0ull, aB = 0ull;
#pragma unroll
            for (int k = 0; k < 8; ++k) {
                ulonglong2 x = xq[k];
                aA = fma2(x.x, wcA[2 * k], aA);
                aB = fma2(x.x, wcB[2 * k], aB);
                aA = fma2(x.y, wcA[2 * k + 1], aA);
                aB = fma2(x.y, wcB[2 * k + 1], aB);
            }
            float2 sA = unpack2(aA), sB = unpack2(aB);
            float xA = sA.x + sA.y + bjA;
            float xB = sB.x + sB.y + bjB;
            float hA = 0.5f * xA * (1.0f + erff(xA * 0.70710678118654752f));
            float hB = 0.5f * xB * (1.0f + erff(xB * 0.70710678118654752f));
            Hs[jA * 34 + r] = pack2(hA, hA);
            Hs[jB * 34 + r] = pack2(hB, hB);
        }
    }
    __syncthreads();

    // phase 2: thread tile 2 rows x 4 cols; per j: 2x LDS.128 + 4 FFMA2, no packs.
    {
        int r0 = (tid >> 3) * 2, d0 = (tid & 7) * 4;
        u64 a00 = 0ull, a01 = 0ull, a10 = 0ull, a11 = 0ull;
#pragma unroll 4
        for (int j = 0; j < 128; ++j) {
            ulonglong2 h01 = *reinterpret_cast<const ulonglong2*>(Hs + j * 34 + r0);
            ulonglong2 u   = *reinterpret_cast<const ulonglong2*>(Us + j * 32 + d0);
            a00 = fma2(h01.x, u.x, a00);  a01 = fma2(h01.x, u.y, a01);
            a10 = fma2(h01.y, u.x, a10);  a11 = fma2(h01.y, u.y, a11);
        }
        float* Vout = (vout_sel == 1) ? g_VA : g_VB;
        float4 c4 = *reinterpret_cast<const float4*>(Us + 4096 + d0);
        float2 p00 = unpack2(a00), p01 = unpack2(a01);
        float2 p10 = unpack2(a10), p11 = unpack2(a11);
        *reinterpret_cast<float4*>(Vout + ((size_t)(b * 2048 + n0 + r0)) * 32 + d0) =
            make_float4(p00.x + c4.x, p00.y + c4.y, p01.x + c4.z, p01.y + c4.w);
        *reinterpret_cast<float4*>(Vout + ((size_t)(b * 2048 + n0 + r0 + 1)) * 32 + d0) =
            make_float4(p10.x + c4.x, p10.y + c4.y, p11.x + c4.z, p11.y + c4.w);
    }
}

// ---------- final projection, fused partial + completion (ticket) ----------
__global__ __launch_bounds__(256) void k_fproj(const float* __restrict__ Wf,
                                               const float* __restrict__ bf,
                                               float* __restrict__ out) {
    __shared__ float wsum[8][10];
    __shared__ int s_last;
    int b = blockIdx.y, ch = blockIdx.x, tid = threadIdx.x;
    int lane = tid & 31, w = tid >> 5;
    float acc[10];
#pragma unroll
    for (int c = 0; c < 10; ++c) acc[c] = 0.f;
    const float* Vb = g_VB + (size_t)b * 65536 + ch * 2048;
#pragma unroll
    for (int q = 0; q < 8; ++q) {
        int k = q * 256 + tid;
        float v = Vb[k];
        const float* wr = Wf + (size_t)(ch * 2048 + k) * 10;
#pragma unroll
        for (int c = 0; c < 10; ++c) acc[c] += v * wr[c];
    }
#pragma unroll
    for (int c = 0; c < 10; ++c) {
#pragma unroll
        for (int s = 16; s > 0; s >>= 1) acc[c] += __shfl_down_sync(0xffffffffu, acc[c], s);
        if (lane == 0) wsum[w][c] = acc[c];
    }
    __syncthreads();
    if (tid < 10) {
        float s = 0.f;
#pragma unroll
        for (int ww = 0; ww < 8; ++ww) s += wsum[ww][tid];
        g_partF[((size_t)(b * 32 + ch)) * 10 + tid] = s;
    }
    __threadfence();
    __syncthreads();
    if (tid == 0) {
        unsigned prev = atomicAdd(&g_tick, 1u);
        s_last = (prev == 511u) ? 1 : 0;
    }
    __syncthreads();
    if (s_last) {
        __threadfence();
        if (tid < 160) {
            int bb = tid / 10, c = tid % 10;
            float s = bf[c];
#pragma unroll
            for (int cc = 0; cc < 32; ++cc) s += g_partF[((size_t)(bb * 32 + cc)) * 10 + c];
            out[tid] = s;
        }
        if (tid == 0) g_tick = 0u;   // reset for next graph replay
    }
}

extern "C" void kernel_launch(void* const* d_in, const int* in_sizes, int n_in,
                              void* d_out, int out_size) {
    const int*   data = (const int*)  d_in[0];
    const float* emb  = (const float*)d_in[1];
    const float* fw1  = (const float*)d_in[2];
    const float* fb1  = (const float*)d_in[3];
    const float* fw2  = (const float*)d_in[4];
    const float* fb2  = (const float*)d_in[5];
    const float* Wf   = (const float*)d_in[6];
    const float* bf   = (const float*)d_in[7];
    float* out = (float*)d_out;

    const int VUPD_SMEM = 20608 + 128 * 34 * 8;   // 55424 bytes -> 4 blocks/SM
    cudaFuncSetAttribute(k_vupd, cudaFuncAttributeMaxDynamicSharedMemorySize, VUPD_SMEM);

    k_gather<<<1024, 256>>>(data, emb);

    // layers i = 3,2,1,0 ; V ping-pong: X -> VA -> VB -> VA -> VB
    int vin = 0;
    for (int it = 0; it < 4; ++it) {
        int layer = 3 - it;
        int vout = (vin == 1) ? 2 : 1;
        k_upart<<<dim3(16, 16), 256>>>(fw2, fb2, vin, layer);
        k_ured<<<65, 256>>>();
        k_vupd<<<dim3(64, 16), 128, VUPD_SMEM>>>(fw1, fb1, vout, layer);
        vin = vout;
    }

    k_fproj<<<dim3(32, 16), 256>>>(Wf, bf, out);
}